// round 10
// baseline (speedup 1.0000x reference)
#include <cuda_runtime.h>
#include <cuda_fp16.h>
#include <cuda_bf16.h>

#define BB   8
#define CIN  256
#define HL   64
#define WL   64
#define CMID 64
#define HHI  128
#define WHI  128
#define EPSV 1e-5f
#define VSTR 144   // V row stride (floats)

// ------------------------- device scratch -------------------------
__device__ float g_WT[CIN * CMID];              // folded transposed 1x1 weights [k][co]
__device__ float g_bias1[CMID];
__device__ float g_EWr[576 * 112];              // folded enc weights [k][m=q*28+kk] (cout=q+4kk)
__device__ float g_bias2r[112];                 // [q*28+kk]
__device__ float g_W1[BB * CMID * HL * WL];     // conv1 output (8,64,64,64)
__device__ float g_Wsm[BB * HHI * WHI * 25];    // softmaxed weights, [b][y][x][25]

// packed fp32x2 FMA (bit-exact 2x fp32 fma)
__device__ __forceinline__ void ffma2(float2& c, float2 a, float2 b) {
    asm("fma.rn.f32x2 %0, %1, %2, %0;"
        : "+l"(reinterpret_cast<unsigned long long&>(c))
        : "l"(reinterpret_cast<unsigned long long&>(a)),
          "l"(reinterpret_cast<unsigned long long&>(b)));
}

// ------------------------- K0: fold BN into weights -------------------------
__global__ void k0_prep(const float* __restrict__ comp_w, const float* __restrict__ comp_b,
                        const float* __restrict__ g1, const float* __restrict__ b1,
                        const float* __restrict__ m1, const float* __restrict__ v1,
                        const float* __restrict__ enc_w, const float* __restrict__ enc_b,
                        const float* __restrict__ g2, const float* __restrict__ b2,
                        const float* __restrict__ m2, const float* __restrict__ v2) {
    int idx = blockIdx.x * 256 + threadIdx.x;
    if (idx < CIN * CMID) {
        int k = idx / CMID, co = idx % CMID;
        float s = g1[co] * rsqrtf(v1[co] + EPSV);
        g_WT[idx] = comp_w[co * CIN + k] * s;
    }
    if (idx < CMID) {
        float s = g1[idx] * rsqrtf(v1[idx] + EPSV);
        g_bias1[idx] = s * (comp_b[idx] - m1[idx]) + b1[idx];
    }
    if (idx < 576 * 112) {
        int k = idx / 112, r = idx % 112;
        int q = r / 28, kk = r % 28;
        float val = 0.f;
        if (kk < 25) {
            int cout = q + 4 * kk;
            float s = g2[cout] * rsqrtf(v2[cout] + EPSV);
            val = enc_w[cout * 576 + k] * s;
        }
        g_EWr[idx] = val;
    }
    if (idx < 112) {
        int q = idx / 28, kk = idx % 28;
        float val = 0.f;
        if (kk < 25) {
            int cout = q + 4 * kk;
            float s = g2[cout] * rsqrtf(v2[cout] + EPSV);
            val = s * (enc_b[cout] - m2[cout]) + b2[cout];
        }
        g_bias2r[idx] = val;
    }
}

// ------------------------- K1: 1x1 conv GEMM + bias + relu (f32x2) ----------------
__global__ __launch_bounds__(256) void k1_conv1(const float* __restrict__ X) {
    __shared__ __align__(16) float Xs[16][128];
    __shared__ __align__(16) float Wts[16][64];
    int tid = threadIdx.x;
    int r = tid >> 5;
    int c = tid & 31;
    int b = blockIdx.y;
    int p0 = blockIdx.x * 128;
    const float* Xb = X + (size_t)b * CIN * HL * WL;

    float2 acc2[4][4];
#pragma unroll
    for (int i = 0; i < 4; i++)
#pragma unroll
        for (int j = 0; j < 4; j++) acc2[i][j] = make_float2(0.f, 0.f);

    for (int k0 = 0; k0 < CIN; k0 += 16) {
        __syncthreads();
#pragma unroll
        for (int i = tid; i < 512; i += 256) {
            int kk = i >> 5, pp = (i & 31) * 4;
            *(float4*)&Xs[kk][pp] = *(const float4*)&Xb[(size_t)(k0 + kk) * (HL * WL) + p0 + pp];
        }
        {
            int kk = tid >> 4, co = (tid & 15) * 4;
            *(float4*)&Wts[kk][co] = *(const float4*)&g_WT[(k0 + kk) * CMID + co];
        }
        __syncthreads();
#pragma unroll
        for (int kk = 0; kk < 16; kk++) {
            float2 w2[4]; float x[4];
            *(float4*)&w2[0] = *(float4*)&Wts[kk][r * 8];
            *(float4*)&w2[2] = *(float4*)&Wts[kk][r * 8 + 4];
            *(float4*)&x[0] = *(float4*)&Xs[kk][c * 4];
            float2 xd[4];
#pragma unroll
            for (int j = 0; j < 4; j++) xd[j] = make_float2(x[j], x[j]);
#pragma unroll
            for (int i = 0; i < 4; i++)
#pragma unroll
                for (int j = 0; j < 4; j++) ffma2(acc2[i][j], w2[i], xd[j]);
        }
    }
#pragma unroll
    for (int i = 0; i < 4; i++) {
        int co0 = r * 8 + 2 * i;
        float b0 = g_bias1[co0], b1 = g_bias1[co0 + 1];
        float4 v0, v1;
        v0.x = fmaxf(acc2[i][0].x + b0, 0.f); v0.y = fmaxf(acc2[i][1].x + b0, 0.f);
        v0.z = fmaxf(acc2[i][2].x + b0, 0.f); v0.w = fmaxf(acc2[i][3].x + b0, 0.f);
        v1.x = fmaxf(acc2[i][0].y + b1, 0.f); v1.y = fmaxf(acc2[i][1].y + b1, 0.f);
        v1.z = fmaxf(acc2[i][2].y + b1, 0.f); v1.w = fmaxf(acc2[i][3].y + b1, 0.f);
        *(float4*)&g_W1[((size_t)b * CMID + co0) * (HL * WL) + p0 + c * 4] = v0;
        *(float4*)&g_W1[((size_t)b * CMID + co0 + 1) * (HL * WL) + p0 + c * 4] = v1;
    }
}

// ------------------------- K2: 3x3 conv GEMM + softmax epilogue -------------------
// M=112 x N=128px x K=576, 8-cin chunks. 256 thr: mg 7 couts, ng 8 px.
__global__ __launch_bounds__(256, 2) void k2_kernelpred() {
    __shared__ __align__(16) float smem[9664];
    float* tin = smem;
    float* twt = smem + 1600;

    int tid = threadIdx.x;
    int mg = tid >> 4;
    int ng = tid & 15;
    int py = ng >> 1;
    int px0 = (ng & 1) * 8;
    int b = blockIdx.y;
    int y0 = (blockIdx.x >> 2) * 8;
    int x0 = (blockIdx.x & 3) * 16;

    int soff[6]; int goff[6]; bool inb[6]; bool val[6];
#pragma unroll
    for (int i = 0; i < 6; i++) {
        int l = tid + i * 256;
        inb[i] = (l < 1440);
        int ls = inb[i] ? l : 0;
        int cin = ls / 180, rem = ls % 180;
        int ty = rem / 18, tx = rem % 18;
        int gy = y0 + ty - 1, gx = x0 + tx - 1;
        val[i] = inb[i] && gy >= 0 && gy < HL && gx >= 0 && gx < WL;
        soff[i] = cin * 200 + ty * 20 + tx;
        goff[i] = (cin * HL + gy) * WL + gx;
    }
    const float* w1base = g_W1 + (size_t)b * CMID * HL * WL;

    float2 acc[7][4];
#pragma unroll
    for (int i = 0; i < 7; i++)
#pragma unroll
        for (int j = 0; j < 4; j++) acc[i][j] = make_float2(0.f, 0.f);

    for (int ch = 0; ch < 8; ch++) {
        __syncthreads();
        const float* w1c = w1base + ch * 8 * HL * WL;
#pragma unroll
        for (int i = 0; i < 6; i++) {
            float v = val[i] ? __ldg(w1c + goff[i]) : 0.f;
            if (inb[i]) tin[soff[i]] = v;
        }
        {
            const float4* src = (const float4*)(g_EWr + ch * 8064);
            float4* dst = (float4*)twt;
#pragma unroll
            for (int i = 0; i < 7; i++) dst[tid + i * 256] = src[tid + i * 256];
            if (tid < 224) dst[tid + 1792] = src[tid + 1792];
        }
        __syncthreads();
#pragma unroll 2
        for (int cin = 0; cin < 8; cin++)
#pragma unroll
            for (int dy = 0; dy < 3; dy++) {
                const float* rp = &tin[cin * 200 + (py + dy) * 20 + px0];
                float2 pe[5];
#pragma unroll
                for (int k = 0; k < 5; k++) pe[k] = *(const float2*)(rp + 2 * k);
                float2 po[4];
#pragma unroll
                for (int k = 0; k < 4; k++) po[k] = make_float2(pe[k].y, pe[k + 1].x);
#pragma unroll
                for (int dx = 0; dx < 3; dx++) {
                    int kl = cin * 9 + dy * 3 + dx;
                    const float* wp = &twt[kl * 112 + mg * 7];
                    const float2* P = (dx == 0) ? pe : (dx == 1) ? po : (pe + 1);
#pragma unroll
                    for (int i = 0; i < 7; i++) {
                        float w = wp[i];
                        float2 w2 = make_float2(w, w);
#pragma unroll
                        for (int j = 0; j < 4; j++) ffma2(acc[i][j], w2, P[j]);
                    }
                }
            }
    }

    float* sL = smem;                                     // [112][66]
    for (int half = 0; half < 2; half++) {
        __syncthreads();
        if ((ng & 1) == half) {
            int colb = py * 8;
#pragma unroll
            for (int i = 0; i < 7; i++) {
                float* row = &sL[(mg * 7 + i) * 66 + colb];
#pragma unroll
                for (int j = 0; j < 4; j++) {
                    row[2 * j] = acc[i][j].x;
                    row[2 * j + 1] = acc[i][j].y;
                }
            }
        }
        __syncthreads();
        {
            int q = tid >> 6;
            int pp = tid & 63;
            int pyy = pp >> 3, pxx = pp & 7;
            int yl = y0 + pyy, xl = x0 + half * 8 + pxx;
            float a[25];
            float mx = -1e30f;
#pragma unroll
            for (int kk = 0; kk < 25; kk++) {
                a[kk] = sL[(q * 28 + kk) * 66 + pp] + __ldg(&g_bias2r[q * 28 + kk]);
                mx = fmaxf(mx, a[kk]);
            }
            float s = 0.f;
#pragma unroll
            for (int kk = 0; kk < 25; kk++) { a[kk] = __expf(a[kk] - mx); s += a[kk]; }
            float inv = 1.0f / s;
            int Y = 2 * yl + (q >> 1), X = 2 * xl + (q & 1);
            float* dst = &g_Wsm[((size_t)(b * HHI + Y) * WHI + X) * 25];
#pragma unroll
            for (int kk = 0; kk < 25; kk++) dst[kk] = a[kk] * inv;
        }
    }
}

// ------------------------- K3: fused bilinear + reassembly ------------------------
// block 128 thr: 4 output rows x full 128 x. grid (32, 8, 4): y-blk, batch, ch-group.
// Per channel: build 12x136 upsampled window V in smem from lo-res X (separable,
// clamp-to-edge, all index math loop-invariant), then 25-tap f32x2 reassembly.
__global__ __launch_bounds__(128) void k3_fused(const float* __restrict__ X,
                                                float* __restrict__ out) {
    __shared__ __align__(16) float V[12 * VSTR];
    int tid = threadIdx.x;
    int ty = tid >> 5;                 // output row in block
    int q = tid & 31;
    int x4 = q * 4;
    int b = blockIdx.y;
    int c0 = blockIdx.z * 64;
    int y0 = blockIdx.x * 4;
    int y = y0 + ty;

    // softmax weights for this thread's 4 output px
    float2 wA[25], wB[25];
    {
        const float* wb = &g_Wsm[((size_t)(b * HHI + y) * WHI + x4) * 25];
#pragma unroll
        for (int k = 0; k < 25; k++) {
            wA[k] = make_float2(__ldg(wb + k),      __ldg(wb + 25 + k));
            wB[k] = make_float2(__ldg(wb + 50 + k), __ldg(wb + 75 + k));
        }
    }

    // ---- loop-invariant V-build descriptors ----
    // column 0: xp = tid (hi-res x = tid-4); column 1 (tid<8): xp2 = tid+128
    int xp1 = tid;
    int xh1 = xp1 - 4;
    bool cv1 = (xh1 >= 0 && xh1 < HHI);
    int xa1 = 0, xb1 = 0; float wxa1 = 0.f, wxb1 = 0.f;
    if (cv1) {
        int rx = xh1 & 1, xl = xh1 >> 1;
        if (rx == 0) { xa1 = max(xl - 1, 0); xb1 = xl; wxa1 = 0.25f; wxb1 = 0.75f; }
        else         { xa1 = xl; xb1 = min(xl + 1, WL - 1); wxa1 = 0.75f; wxb1 = 0.25f; }
    }
    int xp2 = tid + 128;
    int xh2 = xp2 - 4;
    bool cv2 = (tid < 8) && (xh2 < HHI);
    int xa2 = 0, xb2 = 0; float wxa2 = 0.f, wxb2 = 0.f;
    if (cv2) {
        int rx = xh2 & 1, xl = xh2 >> 1;
        if (rx == 0) { xa2 = max(xl - 1, 0); xb2 = xl; wxa2 = 0.25f; wxb2 = 0.75f; }
        else         { xa2 = xl; xb2 = min(xl + 1, WL - 1); wxa2 = 0.75f; wxb2 = 0.25f; }
    }
    // lo-res rows L0..L0+7 (clamped), hi-res row validity mask over p=0..11
    int L0 = (y0 >> 1) - 3;
    int lr[8];
#pragma unroll
    for (int r = 0; r < 8; r++) lr[r] = min(max(L0 + r, 0), HL - 1);
    unsigned rvm = 0;
#pragma unroll
    for (int p = 0; p < 12; p++) {
        int yh = y0 - 4 + p;
        if (yh >= 0 && yh < HHI) rvm |= (1u << p);
    }

    const float* xc = X + ((size_t)(b * CIN + c0)) * (HL * WL);
    float* ob = out + ((size_t)(b * CIN + c0) * HHI + y) * WHI + x4;

    for (int c = 0; c < 64; c++) {
        __syncthreads();
        // ---- phase A: build V[12][136] for this channel ----
        {
            float hx1[8], hx2[8];
#pragma unroll
            for (int r = 0; r < 8; r++) {
                const float* row = xc + lr[r] * WL;
                hx1[r] = cv1 ? (wxa1 * __ldg(row + xa1) + wxb1 * __ldg(row + xb1)) : 0.f;
            }
            if (cv2) {
#pragma unroll
                for (int r = 0; r < 8; r++) {
                    const float* row = xc + lr[r] * WL;
                    hx2[r] = wxa2 * __ldg(row + xa2) + wxb2 * __ldg(row + xb2);
                }
            }
#pragma unroll
            for (int p = 0; p < 12; p++) {
                bool rv = (rvm >> p) & 1;
                float v1, v2;
                if (p & 1) {
                    v1 = 0.75f * hx1[(p + 1) >> 1] + 0.25f * hx1[(p + 3) >> 1];
                    v2 = 0.75f * hx2[(p + 1) >> 1] + 0.25f * hx2[(p + 3) >> 1];
                } else {
                    v1 = 0.25f * hx1[p >> 1] + 0.75f * hx1[(p >> 1) + 1];
                    v2 = 0.25f * hx2[p >> 1] + 0.75f * hx2[(p >> 1) + 1];
                }
                V[p * VSTR + xp1] = rv ? v1 : 0.f;
                if (tid < 8) V[p * VSTR + xp2] = (rv && cv2) ? v2 : 0.f;
            }
        }
        __syncthreads();
        // ---- phase B: 25-tap reassembly from V ----
        float2 aP0 = make_float2(0.f, 0.f), aP1 = make_float2(0.f, 0.f);
#pragma unroll
        for (int i = 0; i < 5; i++) {
            const float* vr = &V[(ty + 2 * i) * VSTR + x4];
            float4 A  = *(const float4*)(vr);
            float4 Bv = *(const float4*)(vr + 4);
            float4 Cv = *(const float4*)(vr + 8);
            float2 pr[6] = { make_float2(A.x, A.y),  make_float2(A.z, A.w),
                             make_float2(Bv.x, Bv.y), make_float2(Bv.z, Bv.w),
                             make_float2(Cv.x, Cv.y), make_float2(Cv.z, Cv.w) };
#pragma unroll
            for (int j = 0; j < 5; j++) {
                ffma2(aP0, wA[i * 5 + j], pr[j]);
                ffma2(aP1, wB[i * 5 + j], pr[j + 1]);
            }
        }
        *(float4*)ob = make_float4(aP0.x, aP0.y, aP1.x, aP1.y);
        ob += (size_t)HHI * WHI;
        xc += HL * WL;
    }
}

// ------------------------- launch -------------------------
extern "C" void kernel_launch(void* const* d_in, const int* in_sizes, int n_in,
                              void* d_out, int out_size) {
    const float* X      = (const float*)d_in[0];
    const float* comp_w = (const float*)d_in[1];
    const float* comp_b = (const float*)d_in[2];
    const float* bn1_g  = (const float*)d_in[3];
    const float* bn1_b  = (const float*)d_in[4];
    const float* bn1_m  = (const float*)d_in[5];
    const float* bn1_v  = (const float*)d_in[6];
    const float* enc_w  = (const float*)d_in[7];
    const float* enc_b  = (const float*)d_in[8];
    const float* bn2_g  = (const float*)d_in[9];
    const float* bn2_b  = (const float*)d_in[10];
    const float* bn2_m  = (const float*)d_in[11];
    const float* bn2_v  = (const float*)d_in[12];
    float* out = (float*)d_out;

    k0_prep<<<252, 256>>>(comp_w, comp_b, bn1_g, bn1_b, bn1_m, bn1_v,
                          enc_w, enc_b, bn2_g, bn2_b, bn2_m, bn2_v);
    k1_conv1<<<dim3(32, 8), 256>>>(X);
    k2_kernelpred<<<dim3(32, 8), 256>>>();
    k3_fused<<<dim3(32, 8, 4), 128>>>(X, out);
}

// round 11
// speedup vs baseline: 1.1226x; 1.1226x over previous
#include <cuda_runtime.h>
#include <cuda_fp16.h>
#include <cuda_bf16.h>

#define BB   8
#define CIN  256
#define HL   64
#define WL   64
#define CMID 64
#define HHI  128
#define WHI  128
#define EPSV 1e-5f
#define VSTR 144   // V row stride (floats)

// ------------------------- device scratch -------------------------
__device__ float g_WT[CIN * CMID];              // folded transposed 1x1 weights [k][co]
__device__ float g_bias1[CMID];
__device__ float g_EWr[576 * 112];              // folded enc weights [k][m=q*28+kk] (cout=q+4kk)
__device__ float g_bias2r[112];                 // [q*28+kk]
__device__ float g_W1[BB * CMID * HL * WL];     // conv1 output (8,64,64,64)
__device__ float g_Wsm[BB * HHI * WHI * 25];    // softmaxed weights, [b][y][x][25]

// packed fp32x2 FMA (bit-exact 2x fp32 fma)
__device__ __forceinline__ void ffma2(float2& c, float2 a, float2 b) {
    asm("fma.rn.f32x2 %0, %1, %2, %0;"
        : "+l"(reinterpret_cast<unsigned long long&>(c))
        : "l"(reinterpret_cast<unsigned long long&>(a)),
          "l"(reinterpret_cast<unsigned long long&>(b)));
}

// ------------------------- K0: fold BN into weights -------------------------
__global__ void k0_prep(const float* __restrict__ comp_w, const float* __restrict__ comp_b,
                        const float* __restrict__ g1, const float* __restrict__ b1,
                        const float* __restrict__ m1, const float* __restrict__ v1,
                        const float* __restrict__ enc_w, const float* __restrict__ enc_b,
                        const float* __restrict__ g2, const float* __restrict__ b2,
                        const float* __restrict__ m2, const float* __restrict__ v2) {
    int idx = blockIdx.x * 256 + threadIdx.x;
    if (idx < CIN * CMID) {
        int k = idx / CMID, co = idx % CMID;
        float s = g1[co] * rsqrtf(v1[co] + EPSV);
        g_WT[idx] = comp_w[co * CIN + k] * s;
    }
    if (idx < CMID) {
        float s = g1[idx] * rsqrtf(v1[idx] + EPSV);
        g_bias1[idx] = s * (comp_b[idx] - m1[idx]) + b1[idx];
    }
    if (idx < 576 * 112) {
        int k = idx / 112, r = idx % 112;
        int q = r / 28, kk = r % 28;
        float val = 0.f;
        if (kk < 25) {
            int cout = q + 4 * kk;
            float s = g2[cout] * rsqrtf(v2[cout] + EPSV);
            val = enc_w[cout * 576 + k] * s;
        }
        g_EWr[idx] = val;
    }
    if (idx < 112) {
        int q = idx / 28, kk = idx % 28;
        float val = 0.f;
        if (kk < 25) {
            int cout = q + 4 * kk;
            float s = g2[cout] * rsqrtf(v2[cout] + EPSV);
            val = s * (enc_b[cout] - m2[cout]) + b2[cout];
        }
        g_bias2r[idx] = val;
    }
}

// ------------------------- K1: 1x1 conv GEMM + bias + relu (f32x2) ----------------
__global__ __launch_bounds__(256) void k1_conv1(const float* __restrict__ X) {
    __shared__ __align__(16) float Xs[16][128];
    __shared__ __align__(16) float Wts[16][64];
    int tid = threadIdx.x;
    int r = tid >> 5;
    int c = tid & 31;
    int b = blockIdx.y;
    int p0 = blockIdx.x * 128;
    const float* Xb = X + (size_t)b * CIN * HL * WL;

    float2 acc2[4][4];
#pragma unroll
    for (int i = 0; i < 4; i++)
#pragma unroll
        for (int j = 0; j < 4; j++) acc2[i][j] = make_float2(0.f, 0.f);

    for (int k0 = 0; k0 < CIN; k0 += 16) {
        __syncthreads();
#pragma unroll
        for (int i = tid; i < 512; i += 256) {
            int kk = i >> 5, pp = (i & 31) * 4;
            *(float4*)&Xs[kk][pp] = *(const float4*)&Xb[(size_t)(k0 + kk) * (HL * WL) + p0 + pp];
        }
        {
            int kk = tid >> 4, co = (tid & 15) * 4;
            *(float4*)&Wts[kk][co] = *(const float4*)&g_WT[(k0 + kk) * CMID + co];
        }
        __syncthreads();
#pragma unroll
        for (int kk = 0; kk < 16; kk++) {
            float2 w2[4]; float x[4];
            *(float4*)&w2[0] = *(float4*)&Wts[kk][r * 8];
            *(float4*)&w2[2] = *(float4*)&Wts[kk][r * 8 + 4];
            *(float4*)&x[0] = *(float4*)&Xs[kk][c * 4];
            float2 xd[4];
#pragma unroll
            for (int j = 0; j < 4; j++) xd[j] = make_float2(x[j], x[j]);
#pragma unroll
            for (int i = 0; i < 4; i++)
#pragma unroll
                for (int j = 0; j < 4; j++) ffma2(acc2[i][j], w2[i], xd[j]);
        }
    }
#pragma unroll
    for (int i = 0; i < 4; i++) {
        int co0 = r * 8 + 2 * i;
        float b0 = g_bias1[co0], b1 = g_bias1[co0 + 1];
        float4 v0, v1;
        v0.x = fmaxf(acc2[i][0].x + b0, 0.f); v0.y = fmaxf(acc2[i][1].x + b0, 0.f);
        v0.z = fmaxf(acc2[i][2].x + b0, 0.f); v0.w = fmaxf(acc2[i][3].x + b0, 0.f);
        v1.x = fmaxf(acc2[i][0].y + b1, 0.f); v1.y = fmaxf(acc2[i][1].y + b1, 0.f);
        v1.z = fmaxf(acc2[i][2].y + b1, 0.f); v1.w = fmaxf(acc2[i][3].y + b1, 0.f);
        *(float4*)&g_W1[((size_t)b * CMID + co0) * (HL * WL) + p0 + c * 4] = v0;
        *(float4*)&g_W1[((size_t)b * CMID + co0 + 1) * (HL * WL) + p0 + c * 4] = v1;
    }
}

// ------------------------- K2: 3x3 conv GEMM + softmax epilogue -------------------
__global__ __launch_bounds__(256, 2) void k2_kernelpred() {
    __shared__ __align__(16) float smem[9664];
    float* tin = smem;
    float* twt = smem + 1600;

    int tid = threadIdx.x;
    int mg = tid >> 4;
    int ng = tid & 15;
    int py = ng >> 1;
    int px0 = (ng & 1) * 8;
    int b = blockIdx.y;
    int y0 = (blockIdx.x >> 2) * 8;
    int x0 = (blockIdx.x & 3) * 16;

    int soff[6]; int goff[6]; bool inb[6]; bool val[6];
#pragma unroll
    for (int i = 0; i < 6; i++) {
        int l = tid + i * 256;
        inb[i] = (l < 1440);
        int ls = inb[i] ? l : 0;
        int cin = ls / 180, rem = ls % 180;
        int ty = rem / 18, tx = rem % 18;
        int gy = y0 + ty - 1, gx = x0 + tx - 1;
        val[i] = inb[i] && gy >= 0 && gy < HL && gx >= 0 && gx < WL;
        soff[i] = cin * 200 + ty * 20 + tx;
        goff[i] = (cin * HL + gy) * WL + gx;
    }
    const float* w1base = g_W1 + (size_t)b * CMID * HL * WL;

    float2 acc[7][4];
#pragma unroll
    for (int i = 0; i < 7; i++)
#pragma unroll
        for (int j = 0; j < 4; j++) acc[i][j] = make_float2(0.f, 0.f);

    for (int ch = 0; ch < 8; ch++) {
        __syncthreads();
        const float* w1c = w1base + ch * 8 * HL * WL;
#pragma unroll
        for (int i = 0; i < 6; i++) {
            float v = val[i] ? __ldg(w1c + goff[i]) : 0.f;
            if (inb[i]) tin[soff[i]] = v;
        }
        {
            const float4* src = (const float4*)(g_EWr + ch * 8064);
            float4* dst = (float4*)twt;
#pragma unroll
            for (int i = 0; i < 7; i++) dst[tid + i * 256] = src[tid + i * 256];
            if (tid < 224) dst[tid + 1792] = src[tid + 1792];
        }
        __syncthreads();
#pragma unroll 2
        for (int cin = 0; cin < 8; cin++)
#pragma unroll
            for (int dy = 0; dy < 3; dy++) {
                const float* rp = &tin[cin * 200 + (py + dy) * 20 + px0];
                float2 pe[5];
#pragma unroll
                for (int k = 0; k < 5; k++) pe[k] = *(const float2*)(rp + 2 * k);
                float2 po[4];
#pragma unroll
                for (int k = 0; k < 4; k++) po[k] = make_float2(pe[k].y, pe[k + 1].x);
#pragma unroll
                for (int dx = 0; dx < 3; dx++) {
                    int kl = cin * 9 + dy * 3 + dx;
                    const float* wp = &twt[kl * 112 + mg * 7];
                    const float2* P = (dx == 0) ? pe : (dx == 1) ? po : (pe + 1);
#pragma unroll
                    for (int i = 0; i < 7; i++) {
                        float w = wp[i];
                        float2 w2 = make_float2(w, w);
#pragma unroll
                        for (int j = 0; j < 4; j++) ffma2(acc[i][j], w2, P[j]);
                    }
                }
            }
    }

    float* sL = smem;                                     // [112][66]
    for (int half = 0; half < 2; half++) {
        __syncthreads();
        if ((ng & 1) == half) {
            int colb = py * 8;
#pragma unroll
            for (int i = 0; i < 7; i++) {
                float* row = &sL[(mg * 7 + i) * 66 + colb];
#pragma unroll
                for (int j = 0; j < 4; j++) {
                    row[2 * j] = acc[i][j].x;
                    row[2 * j + 1] = acc[i][j].y;
                }
            }
        }
        __syncthreads();
        {
            int q = tid >> 6;
            int pp = tid & 63;
            int pyy = pp >> 3, pxx = pp & 7;
            int yl = y0 + pyy, xl = x0 + half * 8 + pxx;
            float a[25];
            float mx = -1e30f;
#pragma unroll
            for (int kk = 0; kk < 25; kk++) {
                a[kk] = sL[(q * 28 + kk) * 66 + pp] + __ldg(&g_bias2r[q * 28 + kk]);
                mx = fmaxf(mx, a[kk]);
            }
            float s = 0.f;
#pragma unroll
            for (int kk = 0; kk < 25; kk++) { a[kk] = __expf(a[kk] - mx); s += a[kk]; }
            float inv = 1.0f / s;
            int Y = 2 * yl + (q >> 1), X = 2 * xl + (q & 1);
            float* dst = &g_Wsm[((size_t)(b * HHI + Y) * WHI + X) * 25];
#pragma unroll
            for (int kk = 0; kk < 25; kk++) dst[kk] = a[kk] * inv;
        }
    }
}

// ------------------------- K3: fused bilinear + reassembly (smem-staged) ----------
// 160 thr (5 warps). tid<128: reassembly of 4 rows x 128 x (4 px each).
// tid<136: V-build (one column each). tid>=128: stage next channel's X rows.
// Per channel: Xs (double-buffered, 8x64) -> V[12][136] -> 25-tap f32x2 reassembly.
__global__ __launch_bounds__(160) void k3_fused(const float* __restrict__ X,
                                                float* __restrict__ out) {
    __shared__ __align__(16) float V[12 * VSTR];
    __shared__ __align__(16) float Xs[2][8][64];
    int tid = threadIdx.x;
    int b = blockIdx.y;
    int c0 = blockIdx.z * 64;
    int y0 = blockIdx.x * 4;

    int ty = (tid >> 5) & 3;
    int x4 = (tid & 31) * 4;
    int y = y0 + ty;

    // softmax weights (reassembly threads only)
    float2 wA[25], wB[25];
    if (tid < 128) {
        const float* wb = &g_Wsm[((size_t)(b * HHI + y) * WHI + x4) * 25];
#pragma unroll
        for (int k = 0; k < 25; k++) {
            wA[k] = make_float2(__ldg(wb + k),      __ldg(wb + 25 + k));
            wB[k] = make_float2(__ldg(wb + 50 + k), __ldg(wb + 75 + k));
        }
    }

    // V-build descriptors: column xp = tid (hi-res x = tid-4)
    bool bld = tid < 136;
    int xh = tid - 4;
    bool cv = bld && (xh >= 0) && (xh < HHI);
    int xa = 0, xb = 0; float wxa = 0.f, wxb = 0.f;
    if (cv) {
        int rx = xh & 1, xl = xh >> 1;
        if (rx == 0) { xa = max(xl - 1, 0); xb = xl; wxa = 0.25f; wxb = 0.75f; }
        else         { xa = xl; xb = min(xl + 1, WL - 1); wxa = 0.75f; wxb = 0.25f; }
    }
    int L0 = (y0 >> 1) - 3;
    int lr[8];
#pragma unroll
    for (int r = 0; r < 8; r++) lr[r] = min(max(L0 + r, 0), HL - 1);
    unsigned rvm = 0;
#pragma unroll
    for (int p = 0; p < 12; p++) {
        int yh = y0 - 4 + p;
        if (yh >= 0 && yh < HHI) rvm |= (1u << p);
    }

    const float* xc = X + ((size_t)(b * CIN + c0)) * (HL * WL);
    float* ob = out + ((size_t)(b * CIN + c0) * HHI + y) * WHI + x4;

    // stage channel 0 into buffer 0 (all threads help)
    if (tid < 128) {
        int r = tid >> 4, j = tid & 15;
        *(float4*)&Xs[0][r][j * 4] = __ldg((const float4*)(xc + lr[r] * WL + j * 4));
    }

    for (int c = 0; c < 64; c++) {
        int buf = c & 1;
        __syncthreads();                       // Xs[buf] staged; V free
        if (bld) {
            float hx[8];
#pragma unroll
            for (int r = 0; r < 8; r++)
                hx[r] = cv ? (wxa * Xs[buf][r][xa] + wxb * Xs[buf][r][xb]) : 0.f;
#pragma unroll
            for (int p = 0; p < 12; p++) {
                float v;
                if (p & 1) v = 0.75f * hx[(p + 1) >> 1] + 0.25f * hx[(p + 3) >> 1];
                else       v = 0.25f * hx[p >> 1] + 0.75f * hx[(p >> 1) + 1];
                V[p * VSTR + tid] = ((rvm >> p) & 1) ? v : 0.f;
            }
        }
        __syncthreads();                       // V ready
        if (tid >= 128) {                      // warp 4: stage next channel
            if (c + 1 < 64) {
                const float* xn = xc + (size_t)(c + 1) * HL * WL;
                int base = (tid - 128) * 4;
#pragma unroll
                for (int k = 0; k < 4; k++) {
                    int i = base + k;
                    int r = i >> 4, j = i & 15;
                    *(float4*)&Xs[buf ^ 1][r][j * 4] =
                        __ldg((const float4*)(xn + lr[r] * WL + j * 4));
                }
            }
        } else {                               // warps 0-3: reassembly
            float2 aP0 = make_float2(0.f, 0.f), aP1 = make_float2(0.f, 0.f);
#pragma unroll
            for (int i = 0; i < 5; i++) {
                const float* vr = &V[(ty + 2 * i) * VSTR + x4];
                float4 A  = *(const float4*)(vr);
                float4 Bv = *(const float4*)(vr + 4);
                float4 Cv = *(const float4*)(vr + 8);
                float2 pr[6] = { make_float2(A.x, A.y),  make_float2(A.z, A.w),
                                 make_float2(Bv.x, Bv.y), make_float2(Bv.z, Bv.w),
                                 make_float2(Cv.x, Cv.y), make_float2(Cv.z, Cv.w) };
#pragma unroll
                for (int j = 0; j < 5; j++) {
                    ffma2(aP0, wA[i * 5 + j], pr[j]);
                    ffma2(aP1, wB[i * 5 + j], pr[j + 1]);
                }
            }
            *(float4*)ob = make_float4(aP0.x, aP0.y, aP1.x, aP1.y);
            ob += (size_t)HHI * WHI;
        }
    }
}

// ------------------------- launch -------------------------
extern "C" void kernel_launch(void* const* d_in, const int* in_sizes, int n_in,
                              void* d_out, int out_size) {
    const float* X      = (const float*)d_in[0];
    const float* comp_w = (const float*)d_in[1];
    const float* comp_b = (const float*)d_in[2];
    const float* bn1_g  = (const float*)d_in[3];
    const float* bn1_b  = (const float*)d_in[4];
    const float* bn1_m  = (const float*)d_in[5];
    const float* bn1_v  = (const float*)d_in[6];
    const float* enc_w  = (const float*)d_in[7];
    const float* enc_b  = (const float*)d_in[8];
    const float* bn2_g  = (const float*)d_in[9];
    const float* bn2_b  = (const float*)d_in[10];
    const float* bn2_m  = (const float*)d_in[11];
    const float* bn2_v  = (const float*)d_in[12];
    float* out = (float*)d_out;

    k0_prep<<<252, 256>>>(comp_w, comp_b, bn1_g, bn1_b, bn1_m, bn1_v,
                          enc_w, enc_b, bn2_g, bn2_b, bn2_m, bn2_v);
    k1_conv1<<<dim3(32, 8), 256>>>(X);
    k2_kernelpred<<<dim3(32, 8), 256>>>();
    k3_fused<<<dim3(32, 8, 4), 160>>>(X, out);
}

// round 12
// speedup vs baseline: 1.6553x; 1.4745x over previous
#include <cuda_runtime.h>
#include <cuda_fp16.h>
#include <cuda_bf16.h>

#define BB   8
#define CIN  256
#define HL   64
#define WL   64
#define CMID 64
#define HHI  128
#define WHI  128
#define HP   136   // padded hi-res (pad 4 each side)
#define EPSV 1e-5f

// ------------------------- device scratch -------------------------
__device__ float g_WT[CIN * CMID];              // folded transposed 1x1 weights [k][co]
__device__ float g_bias1[CMID];
__device__ float g_EWr[576 * 112];              // folded enc weights [k][m=q*28+kk] (cout=q+4kk)
__device__ float g_bias2r[112];                 // [q*28+kk]
__device__ float g_W1[BB * CMID * HL * WL];     // conv1 output (8,64,64,64)
__device__ float g_Wsm[BB * HHI * WHI * 25];    // softmaxed weights, [b][y][x][25]
__device__ __half g_Xuh[(size_t)BB * CIN * HP * HP]; // padded bilinear upsample (fp16)

// packed fp32x2 FMA (bit-exact 2x fp32 fma)
__device__ __forceinline__ void ffma2(float2& c, float2 a, float2 b) {
    asm("fma.rn.f32x2 %0, %1, %2, %0;"
        : "+l"(reinterpret_cast<unsigned long long&>(c))
        : "l"(reinterpret_cast<unsigned long long&>(a)),
          "l"(reinterpret_cast<unsigned long long&>(b)));
}

// ------------------------- K0: fold BN into weights -------------------------
__global__ void k0_prep(const float* __restrict__ comp_w, const float* __restrict__ comp_b,
                        const float* __restrict__ g1, const float* __restrict__ b1,
                        const float* __restrict__ m1, const float* __restrict__ v1,
                        const float* __restrict__ enc_w, const float* __restrict__ enc_b,
                        const float* __restrict__ g2, const float* __restrict__ b2,
                        const float* __restrict__ m2, const float* __restrict__ v2) {
    int idx = blockIdx.x * 256 + threadIdx.x;
    if (idx < CIN * CMID) {
        int k = idx / CMID, co = idx % CMID;
        float s = g1[co] * rsqrtf(v1[co] + EPSV);
        g_WT[idx] = comp_w[co * CIN + k] * s;
    }
    if (idx < CMID) {
        float s = g1[idx] * rsqrtf(v1[idx] + EPSV);
        g_bias1[idx] = s * (comp_b[idx] - m1[idx]) + b1[idx];
    }
    if (idx < 576 * 112) {
        int k = idx / 112, r = idx % 112;
        int q = r / 28, kk = r % 28;
        float val = 0.f;
        if (kk < 25) {
            int cout = q + 4 * kk;
            float s = g2[cout] * rsqrtf(v2[cout] + EPSV);
            val = enc_w[cout * 576 + k] * s;
        }
        g_EWr[idx] = val;
    }
    if (idx < 112) {
        int q = idx / 28, kk = idx % 28;
        float val = 0.f;
        if (kk < 25) {
            int cout = q + 4 * kk;
            float s = g2[cout] * rsqrtf(v2[cout] + EPSV);
            val = s * (enc_b[cout] - m2[cout]) + b2[cout];
        }
        g_bias2r[idx] = val;
    }
}

// ------------------------- K1: 1x1 conv GEMM + bias + relu (f32x2) ----------------
__global__ __launch_bounds__(256) void k1_conv1(const float* __restrict__ X) {
    __shared__ __align__(16) float Xs[16][128];
    __shared__ __align__(16) float Wts[16][64];
    int tid = threadIdx.x;
    int r = tid >> 5;
    int c = tid & 31;
    int b = blockIdx.y;
    int p0 = blockIdx.x * 128;
    const float* Xb = X + (size_t)b * CIN * HL * WL;

    float2 acc2[4][4];
#pragma unroll
    for (int i = 0; i < 4; i++)
#pragma unroll
        for (int j = 0; j < 4; j++) acc2[i][j] = make_float2(0.f, 0.f);

    for (int k0 = 0; k0 < CIN; k0 += 16) {
        __syncthreads();
#pragma unroll
        for (int i = tid; i < 512; i += 256) {
            int kk = i >> 5, pp = (i & 31) * 4;
            *(float4*)&Xs[kk][pp] = *(const float4*)&Xb[(size_t)(k0 + kk) * (HL * WL) + p0 + pp];
        }
        {
            int kk = tid >> 4, co = (tid & 15) * 4;
            *(float4*)&Wts[kk][co] = *(const float4*)&g_WT[(k0 + kk) * CMID + co];
        }
        __syncthreads();
#pragma unroll
        for (int kk = 0; kk < 16; kk++) {
            float2 w2[4]; float x[4];
            *(float4*)&w2[0] = *(float4*)&Wts[kk][r * 8];
            *(float4*)&w2[2] = *(float4*)&Wts[kk][r * 8 + 4];
            *(float4*)&x[0] = *(float4*)&Xs[kk][c * 4];
            float2 xd[4];
#pragma unroll
            for (int j = 0; j < 4; j++) xd[j] = make_float2(x[j], x[j]);
#pragma unroll
            for (int i = 0; i < 4; i++)
#pragma unroll
                for (int j = 0; j < 4; j++) ffma2(acc2[i][j], w2[i], xd[j]);
        }
    }
#pragma unroll
    for (int i = 0; i < 4; i++) {
        int co0 = r * 8 + 2 * i;
        float b0 = g_bias1[co0], b1 = g_bias1[co0 + 1];
        float4 v0, v1;
        v0.x = fmaxf(acc2[i][0].x + b0, 0.f); v0.y = fmaxf(acc2[i][1].x + b0, 0.f);
        v0.z = fmaxf(acc2[i][2].x + b0, 0.f); v0.w = fmaxf(acc2[i][3].x + b0, 0.f);
        v1.x = fmaxf(acc2[i][0].y + b1, 0.f); v1.y = fmaxf(acc2[i][1].y + b1, 0.f);
        v1.z = fmaxf(acc2[i][2].y + b1, 0.f); v1.w = fmaxf(acc2[i][3].y + b1, 0.f);
        *(float4*)&g_W1[((size_t)b * CMID + co0) * (HL * WL) + p0 + c * 4] = v0;
        *(float4*)&g_W1[((size_t)b * CMID + co0 + 1) * (HL * WL) + p0 + c * 4] = v1;
    }
}

// ------------------------- K2: 3x3 conv GEMM + softmax epilogue -------------------
__global__ __launch_bounds__(256, 2) void k2_kernelpred() {
    __shared__ __align__(16) float smem[9664];
    float* tin = smem;
    float* twt = smem + 1600;

    int tid = threadIdx.x;
    int mg = tid >> 4;
    int ng = tid & 15;
    int py = ng >> 1;
    int px0 = (ng & 1) * 8;
    int b = blockIdx.y;
    int y0 = (blockIdx.x >> 2) * 8;
    int x0 = (blockIdx.x & 3) * 16;

    int soff[6]; int goff[6]; bool inb[6]; bool val[6];
#pragma unroll
    for (int i = 0; i < 6; i++) {
        int l = tid + i * 256;
        inb[i] = (l < 1440);
        int ls = inb[i] ? l : 0;
        int cin = ls / 180, rem = ls % 180;
        int ty = rem / 18, tx = rem % 18;
        int gy = y0 + ty - 1, gx = x0 + tx - 1;
        val[i] = inb[i] && gy >= 0 && gy < HL && gx >= 0 && gx < WL;
        soff[i] = cin * 200 + ty * 20 + tx;
        goff[i] = (cin * HL + gy) * WL + gx;
    }
    const float* w1base = g_W1 + (size_t)b * CMID * HL * WL;

    float2 acc[7][4];
#pragma unroll
    for (int i = 0; i < 7; i++)
#pragma unroll
        for (int j = 0; j < 4; j++) acc[i][j] = make_float2(0.f, 0.f);

    for (int ch = 0; ch < 8; ch++) {
        __syncthreads();
        const float* w1c = w1base + ch * 8 * HL * WL;
#pragma unroll
        for (int i = 0; i < 6; i++) {
            float v = val[i] ? __ldg(w1c + goff[i]) : 0.f;
            if (inb[i]) tin[soff[i]] = v;
        }
        {
            const float4* src = (const float4*)(g_EWr + ch * 8064);
            float4* dst = (float4*)twt;
#pragma unroll
            for (int i = 0; i < 7; i++) dst[tid + i * 256] = src[tid + i * 256];
            if (tid < 224) dst[tid + 1792] = src[tid + 1792];
        }
        __syncthreads();
#pragma unroll 2
        for (int cin = 0; cin < 8; cin++)
#pragma unroll
            for (int dy = 0; dy < 3; dy++) {
                const float* rp = &tin[cin * 200 + (py + dy) * 20 + px0];
                float2 pe[5];
#pragma unroll
                for (int k = 0; k < 5; k++) pe[k] = *(const float2*)(rp + 2 * k);
                float2 po[4];
#pragma unroll
                for (int k = 0; k < 4; k++) po[k] = make_float2(pe[k].y, pe[k + 1].x);
#pragma unroll
                for (int dx = 0; dx < 3; dx++) {
                    int kl = cin * 9 + dy * 3 + dx;
                    const float* wp = &twt[kl * 112 + mg * 7];
                    const float2* P = (dx == 0) ? pe : (dx == 1) ? po : (pe + 1);
#pragma unroll
                    for (int i = 0; i < 7; i++) {
                        float w = wp[i];
                        float2 w2 = make_float2(w, w);
#pragma unroll
                        for (int j = 0; j < 4; j++) ffma2(acc[i][j], w2, P[j]);
                    }
                }
            }
    }

    float* sL = smem;                                     // [112][66]
    for (int half = 0; half < 2; half++) {
        __syncthreads();
        if ((ng & 1) == half) {
            int colb = py * 8;
#pragma unroll
            for (int i = 0; i < 7; i++) {
                float* row = &sL[(mg * 7 + i) * 66 + colb];
#pragma unroll
                for (int j = 0; j < 4; j++) {
                    row[2 * j] = acc[i][j].x;
                    row[2 * j + 1] = acc[i][j].y;
                }
            }
        }
        __syncthreads();
        {
            int q = tid >> 6;
            int pp = tid & 63;
            int pyy = pp >> 3, pxx = pp & 7;
            int yl = y0 + pyy, xl = x0 + half * 8 + pxx;
            float a[25];
            float mx = -1e30f;
#pragma unroll
            for (int kk = 0; kk < 25; kk++) {
                a[kk] = sL[(q * 28 + kk) * 66 + pp] + __ldg(&g_bias2r[q * 28 + kk]);
                mx = fmaxf(mx, a[kk]);
            }
            float s = 0.f;
#pragma unroll
            for (int kk = 0; kk < 25; kk++) { a[kk] = __expf(a[kk] - mx); s += a[kk]; }
            float inv = 1.0f / s;
            int Y = 2 * yl + (q >> 1), X = 2 * xl + (q & 1);
            float* dst = &g_Wsm[((size_t)(b * HHI + Y) * WHI + X) * 25];
#pragma unroll
            for (int kk = 0; kk < 25; kk++) dst[kk] = a[kk] * inv;
        }
    }
}

// ------------------------- K_bil: bilinear x2 upsample -> fp16 padded scratch -----
__global__ __launch_bounds__(256) void k_bilinear(const float* __restrict__ X) {
    int gid = blockIdx.x * 256 + threadIdx.x;
    int xg = gid % 17; int t = gid / 17;
    int yp = t % HP;  t /= HP;
    int c = t % CIN;  int b = t / CIN;
    int y = yp - 4;
    float v[8];
#pragma unroll
    for (int u = 0; u < 8; u++) v[u] = 0.f;
    if (y >= 0 && y < HHI) {
        int ry = y & 1, yl = y >> 1;
        int ya, yb; float wya, wyb;
        if (ry == 0) { ya = max(yl - 1, 0); yb = yl; wya = 0.25f; wyb = 0.75f; }
        else         { ya = yl; yb = min(yl + 1, HL - 1); wya = 0.75f; wyb = 0.25f; }
        const float* ra = X + ((size_t)(b * CIN + c) * HL + ya) * WL;
        const float* rb = X + ((size_t)(b * CIN + c) * HL + yb) * WL;
#pragma unroll
        for (int u = 0; u < 8; u++) {
            int x = xg * 8 + u - 4;
            if (x >= 0 && x < WHI) {
                int rx = x & 1, xl = x >> 1;
                int xa, xb; float wxa, wxb;
                if (rx == 0) { xa = max(xl - 1, 0); xb = xl; wxa = 0.25f; wxb = 0.75f; }
                else         { xa = xl; xb = min(xl + 1, WL - 1); wxa = 0.75f; wxb = 0.25f; }
                v[u] = wya * (wxa * __ldg(ra + xa) + wxb * __ldg(ra + xb)) +
                       wyb * (wxa * __ldg(rb + xa) + wxb * __ldg(rb + xb));
            }
        }
    }
    __half2 hv[4];
#pragma unroll
    for (int u = 0; u < 4; u++) hv[u] = __floats2half2_rn(v[2 * u], v[2 * u + 1]);
    *(uint4*)&g_Xuh[(((size_t)(b * CIN + c) * HP) + yp) * HP + xg * 8] = *(uint4*)hv;
}

// ------------------------- K3: reassembly (fp16 loads, 4 fma chains) --------------
// block 128 thr: 4 rows x 32 quads, grid (32, 8, 8). thread: 4 x-px, 32 channels.
__global__ __launch_bounds__(128) void k3_reassemble(float* __restrict__ out) {
    int tid = threadIdx.x;
    int y = blockIdx.x * 4 + (tid >> 5);
    int x4 = (tid & 31) * 4;
    int b = blockIdx.y;
    int c0 = blockIdx.z * 32;

    float2 wA[25], wB[25];
    const float* wb = &g_Wsm[((size_t)(b * HHI + y) * WHI + x4) * 25];
#pragma unroll
    for (int k = 0; k < 25; k++) {
        wA[k] = make_float2(__ldg(wb + k),      __ldg(wb + 25 + k));
        wB[k] = make_float2(__ldg(wb + 50 + k), __ldg(wb + 75 + k));
    }

    const __half* xr = &g_Xuh[(((size_t)(b * CIN + c0) * HP) + y) * HP + x4];
    float* ob = out + ((size_t)(b * CIN + c0) * HHI + y) * WHI + x4;
    const size_t chs = (size_t)HP * HP;

    uint2 cur[15], nxt[15];
#pragma unroll
    for (int i = 0; i < 5; i++) {
        const __half* rp = xr + 2 * i * HP;
        cur[3 * i]     = *(const uint2*)(rp);
        cur[3 * i + 1] = *(const uint2*)(rp + 4);
        cur[3 * i + 2] = *(const uint2*)(rp + 8);
    }

#pragma unroll 2
    for (int c = 0; c < 32; c++) {
        const __half* xn = xr + (c < 31 ? chs : 0);
#pragma unroll
        for (int i = 0; i < 5; i++) {
            const __half* rp = xn + 2 * i * HP;
            nxt[3 * i]     = *(const uint2*)(rp);
            nxt[3 * i + 1] = *(const uint2*)(rp + 4);
            nxt[3 * i + 2] = *(const uint2*)(rp + 8);
        }
        // 4 independent accumulation chains per pixel-pair (even/odd tap rows)
        float2 aP0e = make_float2(0.f, 0.f), aP0o = make_float2(0.f, 0.f);
        float2 aP1e = make_float2(0.f, 0.f), aP1o = make_float2(0.f, 0.f);
#pragma unroll
        for (int i = 0; i < 5; i++) {
            float2 pr[6];
#pragma unroll
            for (int q = 0; q < 3; q++) {
                uint2 rw = cur[3 * i + q];
                pr[2 * q]     = __half22float2(*(const __half2*)&rw.x);
                pr[2 * q + 1] = __half22float2(*(const __half2*)&rw.y);
            }
            float2& a0 = (i & 1) ? aP0o : aP0e;
            float2& a1 = (i & 1) ? aP1o : aP1e;
#pragma unroll
            for (int j = 0; j < 5; j++) {
                ffma2(a0, wA[i * 5 + j], pr[j]);
                ffma2(a1, wB[i * 5 + j], pr[j + 1]);
            }
        }
        float2 aP0 = make_float2(aP0e.x + aP0o.x, aP0e.y + aP0o.y);
        float2 aP1 = make_float2(aP1e.x + aP1o.x, aP1e.y + aP1o.y);
        *(float4*)ob = make_float4(aP0.x, aP0.y, aP1.x, aP1.y);
        ob += (size_t)HHI * WHI;
        xr = xn;
#pragma unroll
        for (int i = 0; i < 15; i++) cur[i] = nxt[i];
    }
}

// ------------------------- launch -------------------------
extern "C" void kernel_launch(void* const* d_in, const int* in_sizes, int n_in,
                              void* d_out, int out_size) {
    const float* X      = (const float*)d_in[0];
    const float* comp_w = (const float*)d_in[1];
    const float* comp_b = (const float*)d_in[2];
    const float* bn1_g  = (const float*)d_in[3];
    const float* bn1_b  = (const float*)d_in[4];
    const float* bn1_m  = (const float*)d_in[5];
    const float* bn1_v  = (const float*)d_in[6];
    const float* enc_w  = (const float*)d_in[7];
    const float* enc_b  = (const float*)d_in[8];
    const float* bn2_g  = (const float*)d_in[9];
    const float* bn2_b  = (const float*)d_in[10];
    const float* bn2_m  = (const float*)d_in[11];
    const float* bn2_v  = (const float*)d_in[12];
    float* out = (float*)d_out;

    k0_prep<<<252, 256>>>(comp_w, comp_b, bn1_g, bn1_b, bn1_m, bn1_v,
                          enc_w, enc_b, bn2_g, bn2_b, bn2_m, bn2_v);
    k1_conv1<<<dim3(32, 8), 256>>>(X);
    k_bilinear<<<18496, 256>>>(X);
    k2_kernelpred<<<dim3(32, 8), 256>>>();
    k3_reassemble<<<dim3(32, 8, 8), 128>>>(out);
}